// round 10
// baseline (speedup 1.0000x reference)
#include <cuda_runtime.h>

#define NROWS   32768
#define DCOLS   2048
#define C4TOT   (DCOLS / 4)            // 512 float4 columns
#define SLABC4  64                     // float4 cols/slab = 256 scalar cols = 32 MB
#define NSLABS  (C4TOT / SLABC4)       // 8
#define SCOLS   (SLABC4 * 4)           // 256 scalar columns per slab
#define EPS     1e-6f
#define QSPACE  ((NROWS / 4) * SLABC4) // 524288 B-work items per slab

// Allocation-free scratch; g_u/g_cnt return to zero every launch sequence.
__device__ float g_u[DCOLS];
__device__ float g_s[DCOLS];
__device__ int   g_cnt[DCOLS];

// ---------------------------------------------------------------------------
// A role: column sum-of-squares for one 32MB slab, grid-strided so it works
// for any number of participating blocks. MLP=4 batched loads.
__device__ __forceinline__ void do_reduce(const float4* __restrict__ x,
                                          int slab, int aIdx, int aBlocks,
                                          int tid) {
    const int c4l = tid & (SLABC4 - 1);            // 0..63
    const int rw  = tid >> 6;                      // 0..3
    const int w   = aIdx * 4 + rw;                 // row worker
    const int W   = aBlocks * 4;                   // total row workers
    const size_t coff = (size_t)slab * SLABC4 + c4l;

    float ax = 0.f, ay = 0.f, az = 0.f, aw = 0.f;
    int r = w;
    for (; r + 3 * W < NROWS; r += 4 * W) {
        float4 v0 = x[(size_t)(r        ) * C4TOT + coff];
        float4 v1 = x[(size_t)(r +     W) * C4TOT + coff];
        float4 v2 = x[(size_t)(r + 2 * W) * C4TOT + coff];
        float4 v3 = x[(size_t)(r + 3 * W) * C4TOT + coff];
        ax = fmaf(v0.x, v0.x, ax); ay = fmaf(v0.y, v0.y, ay);
        az = fmaf(v0.z, v0.z, az); aw = fmaf(v0.w, v0.w, aw);
        ax = fmaf(v1.x, v1.x, ax); ay = fmaf(v1.y, v1.y, ay);
        az = fmaf(v1.z, v1.z, az); aw = fmaf(v1.w, v1.w, aw);
        ax = fmaf(v2.x, v2.x, ax); ay = fmaf(v2.y, v2.y, ay);
        az = fmaf(v2.z, v2.z, az); aw = fmaf(v2.w, v2.w, aw);
        ax = fmaf(v3.x, v3.x, ax); ay = fmaf(v3.y, v3.y, ay);
        az = fmaf(v3.z, v3.z, az); aw = fmaf(v3.w, v3.w, aw);
    }
    for (; r < NROWS; r += W) {
        float4 v = x[(size_t)r * C4TOT + coff];
        ax = fmaf(v.x, v.x, ax); ay = fmaf(v.y, v.y, ay);
        az = fmaf(v.z, v.z, az); aw = fmaf(v.w, v.w, aw);
    }

    __shared__ float sacc[4][SCOLS];
    sacc[rw][c4l * 4 + 0] = ax;
    sacc[rw][c4l * 4 + 1] = ay;
    sacc[rw][c4l * 4 + 2] = az;
    sacc[rw][c4l * 4 + 3] = aw;
    __syncthreads();

    const int scol = slab * SCOLS + tid;           // tid 0..255 -> 256 cols
    float v = sacc[0][tid] + sacc[1][tid] + sacc[2][tid] + sacc[3][tid];
    atomicAdd(&g_u[scol], v);
    __threadfence();                               // publish before counting
    if (atomicAdd(&g_cnt[scol], 1) == aBlocks - 1) {
        float tot = atomicExch(&g_u[scol], 0.0f);  // complete sum + reset
        g_s[scol]   = rsqrtf(tot + EPS);
        g_cnt[scol] = 0;                           // reset for next replay
    }
}

// ---------------------------------------------------------------------------
// B role: y = x * s for one slab, grid-strided, MLP=4 (4 batched ldcs before
// 4 stcs). Reads hit L2 (slab allocated by the previous stage's A role).
__device__ __forceinline__ void do_scale(const float4* __restrict__ x,
                                         float4* __restrict__ y,
                                         int slab, unsigned bIdx,
                                         unsigned bBlocks, int tid) {
    const unsigned stride = bBlocks * 256u;
    const size_t   step   = (size_t)(NROWS / 4) * C4TOT;   // 8192-row stride
    const size_t   soff   = (size_t)slab * SLABC4;

    for (unsigned j = bIdx * 256u + tid; j < QSPACE; j += stride) {
        const int      c4l = j & (SLABC4 - 1);
        const unsigned rq  = j >> 6;
        const size_t base  = (size_t)rq * C4TOT + soff + c4l;

        const float4 s = ((const float4*)g_s)[slab * SLABC4 + c4l];

        float4 v0 = __ldcs(x + base);
        float4 v1 = __ldcs(x + base +     step);
        float4 v2 = __ldcs(x + base + 2 * step);
        float4 v3 = __ldcs(x + base + 3 * step);
        v0.x *= s.x; v0.y *= s.y; v0.z *= s.z; v0.w *= s.w;
        v1.x *= s.x; v1.y *= s.y; v1.z *= s.z; v1.w *= s.w;
        v2.x *= s.x; v2.y *= s.y; v2.z *= s.z; v2.w *= s.w;
        v3.x *= s.x; v3.y *= s.y; v3.z *= s.z; v3.w *= s.w;
        __stcs(y + base,            v0);
        __stcs(y + base +     step, v1);
        __stcs(y + base + 2 * step, v2);
        __stcs(y + base + 3 * step, v3);
    }
}

// ---------------------------------------------------------------------------
// One pipeline stage. Mixed stages split the (even) grid by block parity so
// every SM hosts both roles; single-role stages use the whole grid.
__global__ void __launch_bounds__(256)
stage_kernel(const float4* __restrict__ x, float4* __restrict__ y,
             int aslab, int bslab) {
    const int tid = threadIdx.x;
    if (aslab >= 0 && bslab >= 0) {
        if (blockIdx.x & 1)
            do_reduce(x, aslab, (int)(blockIdx.x >> 1), (int)(gridDim.x >> 1), tid);
        else
            do_scale(x, y, bslab, blockIdx.x >> 1, gridDim.x >> 1, tid);
    } else if (aslab >= 0) {
        do_reduce(x, aslab, (int)blockIdx.x, (int)gridDim.x, tid);
    } else {
        do_scale(x, y, bslab, blockIdx.x, gridDim.x, tid);
    }
}

// ---------------------------------------------------------------------------
extern "C" void kernel_launch(void* const* d_in, const int* in_sizes, int n_in,
                              void* d_out, int out_size) {
    const float4* x = (const float4*)d_in[0];
    float4*       y = (float4*)d_out;

    static int nsm = 0;
    if (nsm == 0) {
        cudaDeviceProp prop;
        cudaGetDeviceProperties(&prop, 0);
        nsm = prop.multiProcessorCount;            // 152 on GB300
    }
    const int GBLK = 8 * nsm;                      // one even wave, 8 blk/SM

    // Pipeline: stage s reduces slab s while scaling slab s-1.
    for (int s = 0; s <= NSLABS; ++s) {
        int aslab = (s < NSLABS) ? s : -1;
        int bslab = (s > 0) ? s - 1 : -1;
        stage_kernel<<<GBLK, 256>>>(x, y, aslab, bslab);
    }
}